// round 6
// baseline (speedup 1.0000x reference)
#include <cuda_runtime.h>

#define NWIRES 11
#define NLAY   4
#define NGATES 88
#define PIX    1024
#define NB     1024

// Per gate: (c1,d1,c2,d2) = (u00.re,u00.im,u01.re,u01.im); SU(2): u10=(-c2,d2), u11=(c1,-d1)
__device__ float4 g_G[NGATES];

__global__ void precompute_gates(const float* __restrict__ w0,
                                 const float* __restrict__ w1) {
    int idx = blockIdx.x * blockDim.x + threadIdx.x;
    if (idx >= NGATES) return;
    const float PI_F = 3.14159265358979323846f;
    int k = idx / 44, rem = idx % 44;
    const float* w = (k == 0) ? w0 : w1;
    float phi   = PI_F * tanhf(w[rem * 3 + 0]);
    float theta = PI_F * tanhf(w[rem * 3 + 1]);
    float omega = PI_F * tanhf(w[rem * 3 + 2]);
    float c = cosf(0.5f * theta), s = sinf(0.5f * theta);
    float apo = 0.5f * (phi + omega), bpo = 0.5f * (phi - omega);
    float are = cosf(apo), aim = -sinf(apo);   // a = exp(-i*apo)
    float bre = cosf(bpo), bim = sinf(bpo);    // b = exp(+i*bpo)
    g_G[idx] = make_float4(are * c, aim * c, -bre * s, -bim * s);
}

// inverse CNOT-chain permutation (gather form); GF(2)-linear in dst.
__device__ __forceinline__ int cinv_idx(int dst, int r) {
    int src = dst;
    for (int q = NWIRES - 1; q >= 0; q--) {
        int cb = NWIRES - 1 - q;
        int tq = q + r; if (tq >= NWIRES) tq -= NWIRES;
        int tbit = NWIRES - 1 - tq;
        src ^= ((src >> cb) & 1) << tbit;
    }
    return src;
}

// SU(2) gate pairing register slots j, j|stride. flip = roles swapped (XOR relabel).
__device__ __forceinline__ void gate_reg(float2 a[8], float4 g, int stride, bool flip) {
    const float c1 = g.x, d1 = flip ? -g.y : g.y, c2 = flip ? -g.z : g.z, d2 = g.w;
    #pragma unroll
    for (int j0 = 0; j0 < 8; j0++) {
        if (j0 & stride) continue;
        const int j1 = j0 | stride;
        float2 a0 = a[j0], a1 = a[j1];
        a[j0].x = c1*a0.x - d1*a0.y + c2*a1.x - d2*a1.y;
        a[j0].y = c1*a0.y + d1*a0.x + c2*a1.y + d2*a1.x;
        a[j1].x = -c2*a0.x - d2*a0.y + c1*a1.x + d1*a1.y;
        a[j1].y = -c2*a0.y + d2*a0.x + c1*a1.y - d1*a1.x;
    }
}

// SU(2) gate on a lane bit (partner via shfl_xor mask m). hi = own amp has bit set.
__device__ __forceinline__ void gate_shfl(float2 a[8], float4 g, int m, int hi) {
    const float csx = g.x;
    const float csy = hi ? -g.y : g.y;
    const float cox = hi ? -g.z : g.z;
    const float coy = g.w;
    #pragma unroll
    for (int j = 0; j < 8; j++) {
        float px = __shfl_xor_sync(0xffffffffu, a[j].x, m);
        float py = __shfl_xor_sync(0xffffffffu, a[j].y, m);
        float ax = a[j].x, ay = a[j].y;
        a[j].x = csx*ax - csy*ay + cox*px - coy*py;
        a[j].y = csx*ay + csy*ax + cox*py + coy*px;
    }
}

__global__ __launch_bounds__(256, 4)
void qsim_kernel(const float* __restrict__ x,
                 const float* __restrict__ y,
                 float* __restrict__ out) {
    // sm[buf][0..2047] = re, sm[buf][2048..4095] = im  (2 x 16 KB)
    __shared__ float sm[2][4096];
    __shared__ short fT[4][256];
    __shared__ short fR[4][8];
    __shared__ float red[8];

    const int b = blockIdx.x, t = threadIdx.x;
    const float* xb = x + (size_t)b * PIX;

    // ---- permutation tables: Cinv(idx,r) = fT[r][idx&255] ^ fR[r][idx>>8] ----
    #pragma unroll
    for (int i2 = t; i2 < 1024; i2 += 256)
        fT[i2 >> 8][i2 & 255] = (short)cinv_idx(i2 & 255, (i2 >> 8) + 1);
    if (t < 32) fR[t >> 3][t & 7] = (short)cinv_idx((t & 7) << 8, (t >> 3) + 1);

    // ---- norm ----
    float ss = 0.0f;
    #pragma unroll
    for (int s8 = 0; s8 < 4; s8++) { float v = xb[t + (s8 << 8)]; ss += v * v; }
    #pragma unroll
    for (int o = 16; o > 0; o >>= 1) ss += __shfl_xor_sync(0xffffffffu, ss, o);
    if ((t & 31) == 0) red[t >> 5] = ss;
    __syncthreads();
    float tot = 0.0f;
    #pragma unroll
    for (int wdx = 0; wdx < 8; wdx++) tot += red[wdx];
    float inv = 1.0f / sqrtf(tot);

    // ---- embedding into sm[0]: amp(2p)=emb[p], amp(2p+1)=0 ----
    #pragma unroll
    for (int s8 = 0; s8 < 4; s8++) {
        int p = t + (s8 << 8);
        sm[0][2 * p]            = xb[p] * inv;
        sm[0][2 * p + 1]        = 0.0f;
        sm[0][2048 + 2 * p]     = 0.0f;
        sm[0][2048 + 2 * p + 1] = 0.0f;
    }
    const float yhalf = 0.5f * y[b];
    const float yc = cosf(yhalf), ys = sinf(yhalf);
    __syncthreads();

    float2 a[8];
    int cur = 0;
    const int tx     = (t >> 2) & 7;                     // pass-3 XOR relabel
    const int p2base = ((t >> 5) << 8) | (t & 31);       // pass-2 base
    const int p3base = ((t >> 2) << 5) | (t & 3);        // pass-3 base

    #pragma unroll 1
    for (int k = 0; k < 2; k++) {
        #pragma unroll 1
        for (int l = 0; l < NLAY; l++) {
            const int gbase = k * 44 + l * 11;
            const int pend = (k == 0 && l == 0) ? 0 : ((l == 0) ? 4 : l);
            const int nxt = cur ^ 1;

            // ===== pass 1: reg bits = i[10:8] (wires 0,1,2); perm folded; cur -> nxt =====
            if (pend == 0) {
                #pragma unroll
                for (int j = 0; j < 8; j++) {
                    int idx = (j << 8) | t;
                    a[j] = make_float2(sm[cur][idx], sm[cur][idx + 2048]);
                }
            } else {
                const int base = fT[pend - 1][t];
                #pragma unroll
                for (int j = 0; j < 8; j++) {
                    int src = base ^ fR[pend - 1][j];
                    a[j] = make_float2(sm[cur][src], sm[cur][src + 2048]);
                }
            }
            gate_reg(a, g_G[gbase + 0], 4, false);
            gate_reg(a, g_G[gbase + 1], 2, false);
            gate_reg(a, g_G[gbase + 2], 1, false);
            #pragma unroll
            for (int j = 0; j < 8; j++) {
                int idx = (j << 8) | t;
                sm[nxt][idx] = a[j].x; sm[nxt][idx + 2048] = a[j].y;
            }
            __syncthreads();

            // ===== pass 2: reg bits = i[7:5] (wires 3,4,5); in-place in nxt =====
            #pragma unroll
            for (int j = 0; j < 8; j++) {
                int idx = p2base | (j << 5);
                a[j] = make_float2(sm[nxt][idx], sm[nxt][idx + 2048]);
            }
            gate_reg(a, g_G[gbase + 3], 4, false);
            gate_reg(a, g_G[gbase + 4], 2, false);
            gate_reg(a, g_G[gbase + 5], 1, false);
            #pragma unroll
            for (int j = 0; j < 8; j++) {
                int idx = p2base | (j << 5);
                sm[nxt][idx] = a[j].x; sm[nxt][idx + 2048] = a[j].y;
            }
            __syncthreads();

            // ===== pass 3: reg bits = i[4:2] (wires 6,7,8) XOR-relabeled (flip trick);
            //       wires 9,10 on lane bits 1,0 via shfl; in-place in nxt =====
            #pragma unroll
            for (int j = 0; j < 8; j++) {
                int idx = p3base | ((j ^ tx) << 2);   // logical slot j, swizzled address
                a[j] = make_float2(sm[nxt][idx], sm[nxt][idx + 2048]);
            }
            // NOTE: addresses are logical-slot-indexed, so slot order within a pair
            // is physical; roles swap where tx bit is set -> flip.
            gate_reg(a, g_G[gbase + 6], 4, (tx >> 2) & 1);
            gate_reg(a, g_G[gbase + 7], 2, (tx >> 1) & 1);
            gate_reg(a, g_G[gbase + 8], 1, tx & 1);
            gate_shfl(a, g_G[gbase + 9], 2, (t >> 1) & 1);     // wire 9 = bit 1
            {
                float4 G = g_G[gbase + 10];                    // wire 10 = bit 0
                if (l == 0) {   // fuse RX(y): F = Rot * RX
                    float c1 = G.x, d1 = G.y, c2 = G.z, d2 = G.w;
                    G = make_float4(c1 * yc + d2 * ys, d1 * yc - c2 * ys,
                                    d1 * ys + c2 * yc, -c1 * ys + d2 * yc);
                }
                gate_shfl(a, G, 1, t & 1);
            }
            #pragma unroll
            for (int j = 0; j < 8; j++) {
                int idx = p3base | ((j ^ tx) << 2);
                sm[nxt][idx] = a[j].x; sm[nxt][idx + 2048] = a[j].y;
            }
            cur = nxt;
            __syncthreads();
        }
    }

    // wait, pass-3 gate_reg on logical slots j: the XOR relabel means slot j holds
    // amp with i[4:2] = j ^ tx... careful reading above: we load a[j] from address
    // with bits (j^tx) -> a[j] holds amp whose i[4:2] = j^tx. Pairing a[j],a[j|s]
    // pairs amps differing in that bit; the one with i-bit=0 is a[j0] iff tx bit=0,
    // else roles swap -> flip=tx bit. (Validated transformation from rounds 3/5.)

    // ---- epilogue: final perm (r=4) folded; probs of even basis states ----
    float* ob = out + (size_t)b * PIX;
    #pragma unroll
    for (int s8 = 0; s8 < 4; s8++) {
        int p = t + (s8 << 8);
        int e = 2 * p;
        int src = fT[3][e & 255] ^ fR[3][e >> 8];
        float re = sm[cur][src], im = sm[cur][src + 2048];
        float pr = (re * re + im * im) * 1024.0f;
        ob[p] = fminf(pr, 1.0f);
    }
}

extern "C" void kernel_launch(void* const* d_in, const int* in_sizes, int n_in,
                              void* d_out, int out_size) {
    const float* x  = (const float*)d_in[0];
    const float* y  = (const float*)d_in[1];
    const float* w0 = (const float*)d_in[2];
    const float* w1 = (const float*)d_in[3];
    float* out = (float*)d_out;

    precompute_gates<<<1, 128>>>(w0, w1);
    qsim_kernel<<<NB, 256>>>(x, y, out);
}

// round 7
// speedup vs baseline: 1.2541x; 1.2541x over previous
#include <cuda_runtime.h>

#define NWIRES 11
#define NLAY   4
#define NGATES 88
#define PIX    1024
#define NB     1024

typedef unsigned long long ull;

// Per gate: (c1,d1,c2,d2) = (u00.re, u00.im, u01.re, u01.im); SU(2): u10=(-c2,d2), u11=(c1,-d1)
__device__ float4 g_G[NGATES];

__global__ void precompute_gates(const float* __restrict__ w0,
                                 const float* __restrict__ w1) {
    int idx = blockIdx.x * blockDim.x + threadIdx.x;
    if (idx >= NGATES) return;
    const float PI_F = 3.14159265358979323846f;
    int k = idx / 44, rem = idx % 44;
    const float* w = (k == 0) ? w0 : w1;
    float phi   = PI_F * tanhf(w[rem * 3 + 0]);
    float theta = PI_F * tanhf(w[rem * 3 + 1]);
    float omega = PI_F * tanhf(w[rem * 3 + 2]);
    float c = cosf(0.5f * theta), s = sinf(0.5f * theta);
    float apo = 0.5f * (phi + omega), bpo = 0.5f * (phi - omega);
    float are = cosf(apo), aim = -sinf(apo);   // a = exp(-i*apo)
    float bre = cosf(bpo), bim = sinf(bpo);    // b = exp(+i*bpo)
    g_G[idx] = make_float4(are * c, aim * c, -bre * s, -bim * s);
}

// inverse CNOT-chain permutation (gather form)
__device__ __forceinline__ int cinv_idx(int dst, int r) {
    int src = dst;
    for (int q = NWIRES - 1; q >= 0; q--) {
        int cb = NWIRES - 1 - q;
        int tq = q + r; if (tq >= NWIRES) tq -= NWIRES;
        int tbit = NWIRES - 1 - tq;
        src ^= ((src >> cb) & 1) << tbit;
    }
    return src;
}
// amp index s -> float offset of its re part in the float4-pair smem layout
__device__ __forceinline__ int fmap(int s) { return ((s >> 1) << 2) | (s & 1); }

// ---- packed f32x2 helpers ----
__device__ __forceinline__ ull pk(float lo, float hi) {
    ull r; asm("mov.b64 %0,{%1,%2};" : "=l"(r) : "f"(lo), "f"(hi)); return r;
}
__device__ __forceinline__ void upk(ull v, float& lo, float& hi) {
    asm("mov.b64 {%0,%1},%2;" : "=f"(lo), "=f"(hi) : "l"(v));
}
__device__ __forceinline__ ull dup2(float v) { return pk(v, v); }
__device__ __forceinline__ ull m2(ull a, ull b) {
    ull d; asm("mul.rn.f32x2 %0,%1,%2;" : "=l"(d) : "l"(a), "l"(b)); return d;
}
__device__ __forceinline__ ull f2(ull a, ull b, ull c) {
    ull d; asm("fma.rn.f32x2 %0,%1,%2,%3;" : "=l"(d) : "l"(a), "l"(b), "l"(c)); return d;
}

// SU(2) gate on an inter-register bit (broadcast packed form). flip swaps 0/1 roles.
__device__ __forceinline__ void gate_reg(ull aRe[8], ull aIm[8], float4 g,
                                         int stride, bool flip) {
    float c1 = g.x, d1 = flip ? -g.y : g.y, c2 = flip ? -g.z : g.z, d2 = g.w;
    ull C1 = dup2(c1), D1 = dup2(d1), ND1 = dup2(-d1);
    ull C2 = dup2(c2), NC2 = dup2(-c2), D2 = dup2(d2), ND2 = dup2(-d2);
    #pragma unroll
    for (int j0 = 0; j0 < 8; j0++) {
        if (j0 & stride) continue;
        int j1 = j0 | stride;
        ull A0r = aRe[j0], A0i = aIm[j0], A1r = aRe[j1], A1i = aIm[j1];
        ull o0r = f2(ND2, A1i, f2(C2, A1r, f2(ND1, A0i, m2(C1, A0r))));
        ull o0i = f2(C2,  A1i, f2(D2, A1r, f2(C1,  A0i, m2(D1, A0r))));
        ull o1r = f2(D1,  A1i, f2(C1, A1r, f2(ND2, A0i, m2(NC2, A0r))));
        ull o1i = f2(C1,  A1i, f2(ND1,A1r, f2(NC2, A0i, m2(D2,  A0r))));
        aRe[j0] = o0r; aIm[j0] = o0i; aRe[j1] = o1r; aIm[j1] = o1i;
    }
}

// SU(2) gate on lane bit 0 (partner via shfl)
__device__ __forceinline__ void gate_shfl(ull aRe[8], ull aIm[8], float4 g, int hi) {
    float sd1 = hi ? -g.y : g.y;     // csy
    float sc2 = hi ? -g.z : g.z;     // cox
    ull CSX = dup2(g.x), CSY = dup2(sd1), NCSY = dup2(-sd1);
    ull COX = dup2(sc2), COY = dup2(g.w), NCOY = dup2(-g.w);
    #pragma unroll
    for (int j = 0; j < 8; j++) {
        ull Pr = __shfl_xor_sync(0xffffffffu, aRe[j], 1);
        ull Pi = __shfl_xor_sync(0xffffffffu, aIm[j], 1);
        ull Or = f2(NCOY, Pi, f2(COX, Pr, f2(NCSY, aIm[j], m2(CSX, aRe[j]))));
        ull Oi = f2(COX,  Pi, f2(COY, Pr, f2(CSX,  aIm[j], m2(CSY, aRe[j]))));
        aRe[j] = Or; aIm[j] = Oi;
    }
}

// SU(2) gate on the packing bit (intra-register butterfly via swapped halves)
__device__ __forceinline__ void gate_intra(ull aRe[8], ull aIm[8], float4 g) {
    float c1 = g.x, d1 = g.y, c2 = g.z, d2 = g.w;
    ull K1 = dup2(c1), K2 = pk(c2, -c2), K3 = pk(-d1, d1), K4 = dup2(-d2);
    ull K5 = pk(d1, -d1), K6 = dup2(d2);
    #pragma unroll
    for (int j = 0; j < 8; j++) {
        float rl, rh, il, ih;
        upk(aRe[j], rl, rh); upk(aIm[j], il, ih);
        ull Sr = pk(rh, rl), Si = pk(ih, il);
        ull Or = f2(K4, Si, f2(K3, aIm[j], f2(K2, Sr, m2(K1, aRe[j]))));
        ull Oi = f2(K2, Si, f2(K1, aIm[j], f2(K6, Sr, m2(K5, aRe[j]))));
        aRe[j] = Or; aIm[j] = Oi;
    }
}

__global__ __launch_bounds__(128)
void qsim_kernel(const float* __restrict__ x,
                 const float* __restrict__ y,
                 float* __restrict__ out) {
    __shared__ float4 sp4[2][1024];  // pair P: (re0,re1,im0,im1) -- 2 x 16 KB double buffer
    __shared__ int fT[4][128];
    __shared__ int fR[4][8];
    __shared__ int fW[4];
    __shared__ float red[4];

    const int b = blockIdx.x, t = threadIdx.x;
    const float* xb = x + (size_t)b * PIX;

    // ---- permutation tables (address-space, XOR-composable) ----
    for (int i2 = t; i2 < 512; i2 += 128) {
        int rr = i2 >> 7, tt = i2 & 127;
        fT[rr][tt] = fmap(cinv_idx(tt << 1, rr + 1));
    }
    if (t < 32) fR[t >> 3][t & 7] = fmap(cinv_idx((t & 7) << 8, (t >> 3) + 1));
    if (t < 4)  fW[t] = fmap(cinv_idx(1, t + 1));

    // ---- norm ----
    float ss = 0.0f;
    #pragma unroll
    for (int i = t; i < PIX; i += 128) { float v = xb[i]; ss += v * v; }
    #pragma unroll
    for (int o = 16; o > 0; o >>= 1) ss += __shfl_xor_sync(0xffffffffu, ss, o);
    if ((t & 31) == 0) red[t >> 5] = ss;
    __syncthreads();
    float inv = 1.0f / sqrtf(red[0] + red[1] + red[2] + red[3]);

    // ---- embedding into buffer 0: pair P = (emb[P], 0 | 0, 0) ----
    #pragma unroll
    for (int s8 = 0; s8 < 8; s8++) {
        int P = t + (s8 << 7);
        sp4[0][P] = make_float4(xb[P] * inv, 0.0f, 0.0f, 0.0f);
    }
    const float yhalf = 0.5f * y[b];
    const float yc = cosf(yhalf), ys = sinf(yhalf);
    __syncthreads();

    ull aRe[8], aIm[8];
    int cur = 0;
    const int t31 = (t >> 1) & 7;
    const int B3x = ((t >> 1) << 4) | (t31 << 1) | (t & 1);
    const int b2  = ((t >> 4) << 7) | (t & 15);

    #pragma unroll 1
    for (int k = 0; k < 2; k++) {
        #pragma unroll 1
        for (int l = 0; l < NLAY; l++) {
            const int gbase = k * 44 + l * 11;
            const int pend = (k == 0 && l == 0) ? 0 : ((l == 0) ? 4 : l);
            const int nxt = cur ^ 1;

            // ===== pass 1: reg bits = i[10:8] (wires 0,1,2); perm folded into gather.
            //       RACE-FREE: reads scattered from cur, writes linear to nxt. =====
            if (pend == 0) {
                #pragma unroll
                for (int r = 0; r < 8; r++) {
                    float4 v = sp4[cur][(r << 7) | t];
                    aRe[r] = pk(v.x, v.y); aIm[r] = pk(v.z, v.w);
                }
            } else {
                const float* smf = (const float*)sp4[cur];
                const int base = fT[pend - 1][t], wv = fW[pend - 1];
                #pragma unroll
                for (int r = 0; r < 8; r++) {
                    int A0 = base ^ fR[pend - 1][r];
                    int A1 = A0 ^ wv;
                    aRe[r] = pk(smf[A0], smf[A1]);
                    aIm[r] = pk(smf[A0 + 2], smf[A1 + 2]);
                }
            }
            gate_reg(aRe, aIm, g_G[gbase + 0], 4, false);
            gate_reg(aRe, aIm, g_G[gbase + 1], 2, false);
            gate_reg(aRe, aIm, g_G[gbase + 2], 1, false);
            #pragma unroll
            for (int r = 0; r < 8; r++) {
                float rl, rh, il, ih;
                upk(aRe[r], rl, rh); upk(aIm[r], il, ih);
                sp4[nxt][(r << 7) | t] = make_float4(rl, rh, il, ih);
            }
            __syncthreads();

            // ===== pass 2: reg bits = i[7:5] (wires 3,4,5); per-thread in-place in nxt =====
            #pragma unroll
            for (int r = 0; r < 8; r++) {
                float4 v = sp4[nxt][b2 | (r << 4)];
                aRe[r] = pk(v.x, v.y); aIm[r] = pk(v.z, v.w);
            }
            gate_reg(aRe, aIm, g_G[gbase + 3], 4, false);
            gate_reg(aRe, aIm, g_G[gbase + 4], 2, false);
            gate_reg(aRe, aIm, g_G[gbase + 5], 1, false);
            #pragma unroll
            for (int r = 0; r < 8; r++) {
                float rl, rh, il, ih;
                upk(aRe[r], rl, rh); upk(aIm[r], il, ih);
                sp4[nxt][b2 | (r << 4)] = make_float4(rl, rh, il, ih);
            }
            __syncthreads();

            // ===== pass 3: reg bits = i[4:2] (wires 6,7,8) XOR-relabeled (flip trick);
            //       wire 9 on lane bit 0 via shfl; wire 10 intra; in-place in nxt =====
            #pragma unroll
            for (int u = 0; u < 8; u++) {
                float4 v = sp4[nxt][B3x ^ (u << 1)];
                aRe[u] = pk(v.x, v.y); aIm[u] = pk(v.z, v.w);
            }
            gate_reg(aRe, aIm, g_G[gbase + 6], 4, (t31 >> 2) & 1);
            gate_reg(aRe, aIm, g_G[gbase + 7], 2, (t31 >> 1) & 1);
            gate_reg(aRe, aIm, g_G[gbase + 8], 1, t31 & 1);
            gate_shfl(aRe, aIm, g_G[gbase + 9], t & 1);
            {
                float4 G = g_G[gbase + 10];
                if (l == 0) {   // fuse RX(y): F = Rot * RX
                    float c1 = G.x, d1 = G.y, c2 = G.z, d2 = G.w;
                    G = make_float4(c1 * yc + d2 * ys, d1 * yc - c2 * ys,
                                    d1 * ys + c2 * yc, -c1 * ys + d2 * yc);
                }
                gate_intra(aRe, aIm, G);
            }
            #pragma unroll
            for (int u = 0; u < 8; u++) {
                float rl, rh, il, ih;
                upk(aRe[u], rl, rh); upk(aIm[u], il, ih);
                sp4[nxt][B3x ^ (u << 1)] = make_float4(rl, rh, il, ih);
            }
            cur = nxt;
            __syncthreads();
        }
    }

    // ---- epilogue: final perm (r=4) folded; probs of even basis states ----
    float* ob = out + (size_t)b * PIX;
    const float* smf = (const float*)sp4[cur];
    const int baseo = fT[3][t];
    #pragma unroll
    for (int s8 = 0; s8 < 8; s8++) {
        int addr = baseo ^ fR[3][s8];
        float re = smf[addr], im = smf[addr + 2];
        float pr = (re * re + im * im) * 1024.0f;
        ob[(s8 << 7) + t] = fminf(pr, 1.0f);
    }
}

extern "C" void kernel_launch(void* const* d_in, const int* in_sizes, int n_in,
                              void* d_out, int out_size) {
    const float* x  = (const float*)d_in[0];
    const float* y  = (const float*)d_in[1];
    const float* w0 = (const float*)d_in[2];
    const float* w1 = (const float*)d_in[3];
    float* out = (float*)d_out;

    precompute_gates<<<1, 128>>>(w0, w1);
    qsim_kernel<<<NB, 128>>>(x, y, out);
}

// round 8
// speedup vs baseline: 1.3293x; 1.0599x over previous
#include <cuda_runtime.h>

#define NWIRES 11
#define NLAY   4
#define NGATES 88
#define PIX    1024
#define NB     1024

typedef unsigned long long ull;

// Per gate: (c1,d1,c2,d2) = (u00.re, u00.im, u01.re, u01.im); SU(2): u10=(-c2,d2), u11=(c1,-d1)
__device__ float4 g_G[NGATES];

__global__ void precompute_gates(const float* __restrict__ w0,
                                 const float* __restrict__ w1) {
    int idx = blockIdx.x * blockDim.x + threadIdx.x;
    if (idx >= NGATES) return;
    const float PI_F = 3.14159265358979323846f;
    int k = idx / 44, rem = idx % 44;
    const float* w = (k == 0) ? w0 : w1;
    float phi   = PI_F * tanhf(w[rem * 3 + 0]);
    float theta = PI_F * tanhf(w[rem * 3 + 1]);
    float omega = PI_F * tanhf(w[rem * 3 + 2]);
    float c = cosf(0.5f * theta), s = sinf(0.5f * theta);
    float apo = 0.5f * (phi + omega), bpo = 0.5f * (phi - omega);
    float are = cosf(apo), aim = -sinf(apo);   // a = exp(-i*apo)
    float bre = cosf(bpo), bim = sinf(bpo);    // b = exp(+i*bpo)
    g_G[idx] = make_float4(are * c, aim * c, -bre * s, -bim * s);
}

// inverse CNOT-chain permutation (gather form); GF(2)-linear in dst.
__device__ __forceinline__ int cinv_idx(int dst, int r) {
    int src = dst;
    for (int q = NWIRES - 1; q >= 0; q--) {
        int cb = NWIRES - 1 - q;
        int tq = q + r; if (tq >= NWIRES) tq -= NWIRES;
        int tbit = NWIRES - 1 - tq;
        src ^= ((src >> cb) & 1) << tbit;
    }
    return src;
}
// amp index s -> float offset of its re part in the float4-pair smem layout (bit permutation => GF(2)-linear)
__device__ __forceinline__ int fmap(int s) { return ((s >> 1) << 2) | (s & 1); }

// ---- packed f32x2 helpers ----
__device__ __forceinline__ ull pk(float lo, float hi) {
    ull r; asm("mov.b64 %0,{%1,%2};" : "=l"(r) : "f"(lo), "f"(hi)); return r;
}
__device__ __forceinline__ void upk(ull v, float& lo, float& hi) {
    asm("mov.b64 {%0,%1},%2;" : "=f"(lo), "=f"(hi) : "l"(v));
}
__device__ __forceinline__ ull dup2(float v) { return pk(v, v); }
__device__ __forceinline__ ull m2(ull a, ull b) {
    ull d; asm("mul.rn.f32x2 %0,%1,%2;" : "=l"(d) : "l"(a), "l"(b)); return d;
}
__device__ __forceinline__ ull f2(ull a, ull b, ull c) {
    ull d; asm("fma.rn.f32x2 %0,%1,%2,%3;" : "=l"(d) : "l"(a), "l"(b), "l"(c)); return d;
}

// SU(2) gate on an inter-register bit (broadcast packed form). flip swaps 0/1 roles.
__device__ __forceinline__ void gate_reg(ull aRe[8], ull aIm[8], float4 g,
                                         int stride, bool flip) {
    float c1 = g.x, d1 = flip ? -g.y : g.y, c2 = flip ? -g.z : g.z, d2 = g.w;
    ull C1 = dup2(c1), D1 = dup2(d1), ND1 = dup2(-d1);
    ull C2 = dup2(c2), NC2 = dup2(-c2), D2 = dup2(d2), ND2 = dup2(-d2);
    #pragma unroll
    for (int j0 = 0; j0 < 8; j0++) {
        if (j0 & stride) continue;
        int j1 = j0 | stride;
        ull A0r = aRe[j0], A0i = aIm[j0], A1r = aRe[j1], A1i = aIm[j1];
        ull o0r = f2(ND2, A1i, f2(C2, A1r, f2(ND1, A0i, m2(C1, A0r))));
        ull o0i = f2(C2,  A1i, f2(D2, A1r, f2(C1,  A0i, m2(D1, A0r))));
        ull o1r = f2(D1,  A1i, f2(C1, A1r, f2(ND2, A0i, m2(NC2, A0r))));
        ull o1i = f2(C1,  A1i, f2(ND1,A1r, f2(NC2, A0i, m2(D2,  A0r))));
        aRe[j0] = o0r; aIm[j0] = o0i; aRe[j1] = o1r; aIm[j1] = o1i;
    }
}

// SU(2) gate on lane bit 0 (partner via shfl)
__device__ __forceinline__ void gate_shfl(ull aRe[8], ull aIm[8], float4 g, int hi) {
    float sd1 = hi ? -g.y : g.y;     // csy
    float sc2 = hi ? -g.z : g.z;     // cox
    ull CSX = dup2(g.x), CSY = dup2(sd1), NCSY = dup2(-sd1);
    ull COX = dup2(sc2), COY = dup2(g.w), NCOY = dup2(-g.w);
    #pragma unroll
    for (int j = 0; j < 8; j++) {
        ull Pr = __shfl_xor_sync(0xffffffffu, aRe[j], 1);
        ull Pi = __shfl_xor_sync(0xffffffffu, aIm[j], 1);
        ull Or = f2(NCOY, Pi, f2(COX, Pr, f2(NCSY, aIm[j], m2(CSX, aRe[j]))));
        ull Oi = f2(COX,  Pi, f2(COY, Pr, f2(CSX,  aIm[j], m2(CSY, aRe[j]))));
        aRe[j] = Or; aIm[j] = Oi;
    }
}

// SU(2) gate on the packing bit (intra-register butterfly via swapped halves)
__device__ __forceinline__ void gate_intra(ull aRe[8], ull aIm[8], float4 g) {
    float c1 = g.x, d1 = g.y, c2 = g.z, d2 = g.w;
    ull K1 = dup2(c1), K2 = pk(c2, -c2), K3 = pk(-d1, d1), K4 = dup2(-d2);
    ull K5 = pk(d1, -d1), K6 = dup2(d2);
    #pragma unroll
    for (int j = 0; j < 8; j++) {
        float rl, rh, il, ih;
        upk(aRe[j], rl, rh); upk(aIm[j], il, ih);
        ull Sr = pk(rh, rl), Si = pk(ih, il);
        ull Or = f2(K4, Si, f2(K3, aIm[j], f2(K2, Sr, m2(K1, aRe[j]))));
        ull Oi = f2(K2, Si, f2(K1, aIm[j], f2(K6, Sr, m2(K5, aRe[j]))));
        aRe[j] = Or; aIm[j] = Oi;
    }
}

__global__ __launch_bounds__(128, 7)
void qsim_kernel(const float* __restrict__ x,
                 const float* __restrict__ y,
                 float* __restrict__ out) {
    __shared__ float4 sp4[1024];   // pair P: (re0,re1,im0,im1) -- 16 KB single buffer
    __shared__ int fR[4][8];       // fmap(Cinv(j<<8, r))
    __shared__ int fW[4];          // fmap(Cinv(1, r))
    __shared__ float red[4];
    float* smf = (float*)sp4;

    const int b = blockIdx.x, t = threadIdx.x;
    const float* xb = x + (size_t)b * PIX;

    // ---- tiny perm tables + per-thread bases (GF(2)-linear decomposition) ----
    if (t < 32) fR[t >> 3][t & 7] = fmap(cinv_idx((t & 7) << 8, (t >> 3) + 1));
    if (t < 4)  fW[t] = fmap(cinv_idx(1, t + 1));
    int baseR[4];
    #pragma unroll
    for (int r = 0; r < 4; r++) baseR[r] = fmap(cinv_idx(t << 1, r + 1));

    // ---- norm ----
    float ss = 0.0f;
    #pragma unroll
    for (int i = t; i < PIX; i += 128) { float v = xb[i]; ss += v * v; }
    #pragma unroll
    for (int o = 16; o > 0; o >>= 1) ss += __shfl_xor_sync(0xffffffffu, ss, o);
    if ((t & 31) == 0) red[t >> 5] = ss;
    __syncthreads();
    float inv = 1.0f / sqrtf(red[0] + red[1] + red[2] + red[3]);

    // ---- embedding: pair P = (emb[P], 0 | 0, 0) ----
    #pragma unroll
    for (int s8 = 0; s8 < 8; s8++) {
        int P = t + (s8 << 7);
        sp4[P] = make_float4(xb[P] * inv, 0.0f, 0.0f, 0.0f);
    }
    const float yhalf = 0.5f * y[b];
    const float yc = cosf(yhalf), ys = sinf(yhalf);
    __syncthreads();

    ull aRe[8], aIm[8];
    const int t31 = (t >> 1) & 7;
    const int B3x = ((t >> 1) << 4) | (t31 << 1) | (t & 1);
    const int b2  = ((t >> 4) << 7) | (t & 15);

    #pragma unroll 1
    for (int k = 0; k < 2; k++) {
        #pragma unroll 1
        for (int l = 0; l < NLAY; l++) {
            const int gbase = k * 44 + l * 11;
            const int pend = (k == 0 && l == 0) ? 0 : ((l == 0) ? 4 : l);

            // ===== pass 1: reg bits = i[10:8] (wires 0,1,2); perm folded into gather.
            //       Single buffer: ALL scattered reads complete (barrier after the
            //       register-only gates) before ANY linear write. =====
            if (pend == 0) {
                #pragma unroll
                for (int r = 0; r < 8; r++) {
                    float4 v = sp4[(r << 7) | t];
                    aRe[r] = pk(v.x, v.y); aIm[r] = pk(v.z, v.w);
                }
            } else {
                const int base = baseR[pend - 1], wv = fW[pend - 1];
                #pragma unroll
                for (int r = 0; r < 8; r++) {
                    int A0 = base ^ fR[pend - 1][r];
                    int A1 = A0 ^ wv;
                    aRe[r] = pk(smf[A0], smf[A1]);
                    aIm[r] = pk(smf[A0 + 2], smf[A1 + 2]);
                }
            }
            gate_reg(aRe, aIm, g_G[gbase + 0], 4, false);
            gate_reg(aRe, aIm, g_G[gbase + 1], 2, false);
            gate_reg(aRe, aIm, g_G[gbase + 2], 1, false);
            __syncthreads();   // reads-before-writes fence (race fix)
            #pragma unroll
            for (int r = 0; r < 8; r++) {
                float rl, rh, il, ih;
                upk(aRe[r], rl, rh); upk(aIm[r], il, ih);
                sp4[(r << 7) | t] = make_float4(rl, rh, il, ih);
            }
            __syncthreads();

            // ===== pass 2: reg bits = i[7:5] (wires 3,4,5); per-thread in-place safe =====
            #pragma unroll
            for (int r = 0; r < 8; r++) {
                float4 v = sp4[b2 | (r << 4)];
                aRe[r] = pk(v.x, v.y); aIm[r] = pk(v.z, v.w);
            }
            gate_reg(aRe, aIm, g_G[gbase + 3], 4, false);
            gate_reg(aRe, aIm, g_G[gbase + 4], 2, false);
            gate_reg(aRe, aIm, g_G[gbase + 5], 1, false);
            #pragma unroll
            for (int r = 0; r < 8; r++) {
                float rl, rh, il, ih;
                upk(aRe[r], rl, rh); upk(aIm[r], il, ih);
                sp4[b2 | (r << 4)] = make_float4(rl, rh, il, ih);
            }
            __syncthreads();

            // ===== pass 3: reg bits = i[4:2] (wires 6,7,8) XOR-relabeled (flip trick);
            //       wire 9 shfl on lane bit 0; wire 10 intra; per-thread in-place safe =====
            #pragma unroll
            for (int u = 0; u < 8; u++) {
                float4 v = sp4[B3x ^ (u << 1)];
                aRe[u] = pk(v.x, v.y); aIm[u] = pk(v.z, v.w);
            }
            gate_reg(aRe, aIm, g_G[gbase + 6], 4, (t31 >> 2) & 1);
            gate_reg(aRe, aIm, g_G[gbase + 7], 2, (t31 >> 1) & 1);
            gate_reg(aRe, aIm, g_G[gbase + 8], 1, t31 & 1);
            gate_shfl(aRe, aIm, g_G[gbase + 9], t & 1);
            {
                float4 G = g_G[gbase + 10];
                if (l == 0) {   // fuse RX(y): F = Rot * RX
                    float c1 = G.x, d1 = G.y, c2 = G.z, d2 = G.w;
                    G = make_float4(c1 * yc + d2 * ys, d1 * yc - c2 * ys,
                                    d1 * ys + c2 * yc, -c1 * ys + d2 * yc);
                }
                gate_intra(aRe, aIm, G);
            }
            #pragma unroll
            for (int u = 0; u < 8; u++) {
                float rl, rh, il, ih;
                upk(aRe[u], rl, rh); upk(aIm[u], il, ih);
                sp4[B3x ^ (u << 1)] = make_float4(rl, rh, il, ih);
            }
            __syncthreads();
        }
    }

    // ---- epilogue: final perm (r=4) folded; probs of even basis states ----
    float* ob = out + (size_t)b * PIX;
    const int baseo = baseR[3];
    #pragma unroll
    for (int s8 = 0; s8 < 8; s8++) {
        int addr = baseo ^ fR[3][s8];
        float re = smf[addr], im = smf[addr + 2];
        float pr = (re * re + im * im) * 1024.0f;
        ob[(s8 << 7) + t] = fminf(pr, 1.0f);
    }
}

extern "C" void kernel_launch(void* const* d_in, const int* in_sizes, int n_in,
                              void* d_out, int out_size) {
    const float* x  = (const float*)d_in[0];
    const float* y  = (const float*)d_in[1];
    const float* w0 = (const float*)d_in[2];
    const float* w1 = (const float*)d_in[3];
    float* out = (float*)d_out;

    precompute_gates<<<1, 128>>>(w0, w1);
    qsim_kernel<<<NB, 128>>>(x, y, out);
}